// round 4
// baseline (speedup 1.0000x reference)
#include <cuda_runtime.h>
#include <cuda_fp16.h>
#include <cstdint>

#define N_NODES 50000
#define FDIM 128
#define E_EDGES 800000

// Scratch (static __device__ arrays — no allocations allowed). 16B-aligned.
__device__ __align__(16) float  g_agg[N_NODES * FDIM];     // 25.6 MB
__device__ __align__(16) float  g_cnt[N_NODES];
__device__ __align__(16) float  g_inv[N_NODES];
__device__ __align__(16) float  g_h1[N_NODES * FDIM];      // 25.6 MB
__device__ __align__(16) float  g_h2[N_NODES * FDIM];      // 25.6 MB
__device__ __align__(16) __half g_ab[N_NODES * 512];       // 51.2 MB : [A(256)|B(256)] fp16

// ---------------------------------------------------------------------------
__global__ void zero_all_kernel() {
    int i = blockIdx.x * blockDim.x + threadIdx.x;
    if (i < N_NODES * FDIM) g_agg[i] = 0.0f;
    if (i < N_NODES) g_cnt[i] = 0.0f;
}
__global__ void zero_agg_kernel() {
    int i = blockIdx.x * blockDim.x + threadIdx.x;
    if (i < N_NODES * FDIM) g_agg[i] = 0.0f;
}
__global__ void inv_kernel() {
    int i = blockIdx.x * blockDim.x + threadIdx.x;
    if (i < N_NODES) g_inv[i] = 1.0f / fmaxf(g_cnt[i], 1.0f);
}

// ---------------------------------------------------------------------------
// Scatter: warp per edge. agg[dst] += x[src] (+ cnt[dst] += 1 once).
// ---------------------------------------------------------------------------
template<bool CNT>
__global__ void scatter_kernel(const float4* __restrict__ x,
                               const int* __restrict__ ei) {
    int w = (blockIdx.x * blockDim.x + threadIdx.x) >> 5;
    int lane = threadIdx.x & 31;
    if (w >= E_EDGES) return;
    int s = ei[w];
    int d = ei[E_EDGES + w];
    float4 v = x[(long long)s * 32 + lane];
    float* p = g_agg + ((long long)d * FDIM + lane * 4);
    asm volatile("red.global.add.v4.f32 [%0], {%1,%2,%3,%4};"
                 :: "l"(p), "f"(v.x), "f"(v.y), "f"(v.z), "f"(v.w) : "memory");
    if (CNT && lane == 0) atomicAdd(g_cnt + d, 1.0f);
}

// ---------------------------------------------------------------------------
// Tensor-core GEMM (tf32 mma.sync, A split hi/lo, W single-rounded tf32),
// software-pipelined: LDGs for tile kt+1 issued between the barriers, hidden
// under the MMA stream of tile kt.
//   C[r, j] = act( sum_k A1[r,k]*W1[j,k] (+ A2[r,k]*W2[j,k]) + bias[j] )
//   DUAL:   logical K = 256 (first 128 from A1/W1, second from A2/W2)
//   SPLITW: dout = 512, K = 128; W for col j: Wm1[(j&255)*256 + (j>>8)*128 + k]
//   SCALE:  A1 rows scaled by g_inv[r] at load (fused mean-normalize)
// BM=128, BN=64, BK=32, 256 threads (8 warps: 4 in M x 2 in N), warp 32x32.
// ---------------------------------------------------------------------------
__device__ __forceinline__ float tf32r(float v) {
    uint32_t u;
    asm("cvt.rna.tf32.f32 %0, %1;" : "=r"(u) : "f"(v));
    return __uint_as_float(u);
}
__device__ __forceinline__ void mma_tf32(float4& c, const float4 a, const float2 b) {
    asm volatile(
        "mma.sync.aligned.m16n8k8.row.col.f32.tf32.tf32.f32 "
        "{%0,%1,%2,%3}, {%4,%5,%6,%7}, {%8,%9}, {%0,%1,%2,%3};\n"
        : "+f"(c.x), "+f"(c.y), "+f"(c.z), "+f"(c.w)
        : "r"(__float_as_uint(a.x)), "r"(__float_as_uint(a.y)),
          "r"(__float_as_uint(a.z)), "r"(__float_as_uint(a.w)),
          "r"(__float_as_uint(b.x)), "r"(__float_as_uint(b.y)));
}
__device__ __forceinline__ void store2(float* p, float a, float b) {
    *reinterpret_cast<float2*>(p) = make_float2(a, b);
}
__device__ __forceinline__ void store2(__half* p, float a, float b) {
    *reinterpret_cast<__half2*>(p) = __floats2half2_rn(a, b);
}

template<bool DUAL, bool RELU, bool SPLITW, bool SCALE, typename OUT>
__global__ __launch_bounds__(256, 2)
void gemm_kernel(const float* __restrict__ A1, const float* __restrict__ A2,
                 const float* __restrict__ W1, const float* __restrict__ W2,
                 const float* __restrict__ bias, int bias_len,
                 OUT* __restrict__ C, int n_rows, int dout,
                 const float* __restrict__ inv) {
    __shared__ float sAhi[4096];   // (ks,mtile): 128 floats = lane*4 + reg
    __shared__ float sAlo[4096];
    __shared__ float sB[2048];     // (ks,ntile): 64 floats = lane*2 + reg

    const int tid = threadIdx.x;
    const int lane = tid & 31;
    const int wid = tid >> 5;
    const int wm = wid & 3;        // warp row group (32 rows)
    const int wn = wid >> 2;       // warp col group (32 cols)
    const int r0 = blockIdx.x * 128;
    const int n0 = blockIdx.y * 64;
    const int NKT = DUAL ? 8 : 4;  // 32-wide k tiles

    float4 acc[2][4];
#pragma unroll
    for (int i = 0; i < 2; i++)
#pragma unroll
        for (int j = 0; j < 4; j++) acc[i][j] = make_float4(0.f, 0.f, 0.f, 0.f);

    // Per-thread row scales (rows staged by this thread are fixed across kt)
    float sc[4];
#pragma unroll
    for (int it = 0; it < 4; it++) {
        int r = r0 + ((tid + it * 256) >> 3);
        sc[it] = SCALE ? ((r < n_rows) ? inv[r] : 1.0f) : 1.0f;
    }

    float4 pA[4], pB[2];
    auto load_tile = [&](int kt) {
        const float* Asrc = (DUAL && kt >= 4) ? A2 : A1;
        const float* Wsrc = (DUAL && kt >= 4) ? W2 : W1;
        const int kb = (kt & 3) * 32;
#pragma unroll
        for (int it = 0; it < 4; it++) {
            int id = tid + it * 256;
            int row = id >> 3, c0 = (id & 7) * 4;
            int r = r0 + row;
            pA[it] = make_float4(0.f, 0.f, 0.f, 0.f);
            if (r < n_rows)
                pA[it] = *reinterpret_cast<const float4*>(Asrc + (size_t)r * FDIM + kb + c0);
        }
#pragma unroll
        for (int it = 0; it < 2; it++) {
            int id = tid + it * 256;
            int row = id >> 3, c0 = (id & 7) * 4;
            int jcol = n0 + row;
            const float* wp;
            if (SPLITW) wp = W1 + (jcol & 255) * 256 + ((jcol >> 8) * 128) + kb + c0;
            else        wp = Wsrc + (size_t)jcol * FDIM + kb + c0;
            pB[it] = *reinterpret_cast<const float4*>(wp);
        }
    };

    auto stage = [&](int kt) {
        const bool usc = SCALE && (kt < 4);
#pragma unroll
        for (int it = 0; it < 4; it++) {
            int id = tid + it * 256;
            int row = id >> 3, c0 = (id & 7) * 4, ks = c0 >> 3;
            float v[4] = {pA[it].x, pA[it].y, pA[it].z, pA[it].w};
            if (usc) {
#pragma unroll
                for (int j = 0; j < 4; j++) v[j] *= sc[it];
            }
            int regb = (((row & 15) >= 8) ? 1 : 0) + (((c0 & 7) >= 4) ? 2 : 0);
            int tb = (ks * 8 + (row >> 4)) * 128;
            int lb = (row & 7) * 4;
#pragma unroll
            for (int j = 0; j < 4; j++) {
                float hi = tf32r(v[j]);
                sAhi[tb + (lb + j) * 4 + regb] = hi;
                sAlo[tb + (lb + j) * 4 + regb] = tf32r(v[j] - hi);
            }
        }
#pragma unroll
        for (int it = 0; it < 2; it++) {
            int id = tid + it * 256;
            int row = id >> 3, c0 = (id & 7) * 4, ks = c0 >> 3;
            int bb = (ks * 8 + (row >> 3)) * 64;
            int blb = (row & 7) * 4;
            int bre = ((c0 & 7) >= 4) ? 1 : 0;
            float v[4] = {pB[it].x, pB[it].y, pB[it].z, pB[it].w};
#pragma unroll
            for (int j = 0; j < 4; j++)
                sB[bb + (blb + j) * 2 + bre] = tf32r(v[j]);
        }
    };

    load_tile(0);
    for (int kt = 0; kt < NKT; kt++) {
        stage(kt);
        __syncthreads();
        if (kt + 1 < NKT) load_tile(kt + 1);   // LDGs overlap compute below
#pragma unroll
        for (int ks = 0; ks < 4; ks++) {
            float4 ahi[2], alo[2];
#pragma unroll
            for (int mt2 = 0; mt2 < 2; mt2++) {
                int base = ((ks * 8 + wm * 2 + mt2) * 32 + lane) * 4;
                ahi[mt2] = *reinterpret_cast<const float4*>(sAhi + base);
                alo[mt2] = *reinterpret_cast<const float4*>(sAlo + base);
            }
#pragma unroll
            for (int nt = 0; nt < 4; nt++) {
                float2 b = *reinterpret_cast<const float2*>(
                    sB + (ks * 8 + wn * 4 + nt) * 64 + lane * 2);
#pragma unroll
                for (int mt2 = 0; mt2 < 2; mt2++) {
                    mma_tf32(acc[mt2][nt], ahi[mt2], b);
                    mma_tf32(acc[mt2][nt], alo[mt2], b);
                }
            }
        }
        __syncthreads();
    }

    // ---- epilogue ----
    const int g = lane >> 2, tg = lane & 3;
#pragma unroll
    for (int mt2 = 0; mt2 < 2; mt2++) {
        int Rb = r0 + (wm * 2 + mt2) * 16;
#pragma unroll
        for (int nt = 0; nt < 4; nt++) {
            int Cb = n0 + (wn * 4 + nt) * 8;
            float4 c = acc[mt2][nt];
            float2 bv = make_float2(0.f, 0.f);
            if (bias != nullptr && Cb < bias_len)
                bv = *reinterpret_cast<const float2*>(bias + Cb + tg * 2);
            float lx = c.x + bv.x, ly = c.y + bv.y;
            float hx = c.z + bv.x, hy = c.w + bv.y;
            if (RELU) {
                lx = fmaxf(lx, 0.f); ly = fmaxf(ly, 0.f);
                hx = fmaxf(hx, 0.f); hy = fmaxf(hy, 0.f);
            }
            int r1 = Rb + g, r2 = Rb + g + 8;
            if (r1 < n_rows) store2(C + (size_t)r1 * dout + Cb + tg * 2, lx, ly);
            if (r2 < n_rows) store2(C + (size_t)r2 * dout + Cb + tg * 2, hx, hy);
        }
    }
}

// ---------------------------------------------------------------------------
// Edge MLP epilogue: out[e] = sum_j relu(A[src,j] + B[dst,j]) * w2[j] + b2
// AB in fp16; warp per edge; lane covers 8 consecutive features per half.
// ---------------------------------------------------------------------------
__global__ void edge_kernel(const int* __restrict__ ei,
                            const float4* __restrict__ w2,
                            const float* __restrict__ b2,
                            float* __restrict__ out) {
    int w = (blockIdx.x * blockDim.x + threadIdx.x) >> 5;
    int lane = threadIdx.x & 31;
    if (w >= E_EDGES) return;
    int s = ei[w];
    int d = ei[E_EDGES + w];
    const __half* abh = g_ab;
    uint4 ua = *(reinterpret_cast<const uint4*>(abh + (size_t)s * 512) + lane);
    uint4 ub = *(reinterpret_cast<const uint4*>(abh + (size_t)d * 512 + 256) + lane);
    float4 w0 = w2[lane * 2], w1 = w2[lane * 2 + 1];
    const __half2* ha = reinterpret_cast<const __half2*>(&ua);
    const __half2* hb = reinterpret_cast<const __half2*>(&ub);
    float acc = 0.0f;
    float wf[8] = {w0.x, w0.y, w0.z, w0.w, w1.x, w1.y, w1.z, w1.w};
#pragma unroll
    for (int q = 0; q < 4; q++) {
        float2 a = __half22float2(ha[q]);
        float2 b = __half22float2(hb[q]);
        acc += fmaxf(a.x + b.x, 0.0f) * wf[q * 2];
        acc += fmaxf(a.y + b.y, 0.0f) * wf[q * 2 + 1];
    }
#pragma unroll
    for (int o = 16; o; o >>= 1) acc += __shfl_xor_sync(0xffffffffu, acc, o);
    if (lane == 0) out[w] = acc + b2[0];
}

// ---------------------------------------------------------------------------
extern "C" void kernel_launch(void* const* d_in, const int* in_sizes, int n_in,
                              void* d_out, int out_size) {
    const float* x   = (const float*)d_in[0];
    const int*   ei  = (const int*)d_in[1];     // int32 (JAX x64 disabled)
    const float* W1l = (const float*)d_in[2];
    const float* b1l = (const float*)d_in[3];
    const float* W1r = (const float*)d_in[4];
    const float* W2l = (const float*)d_in[5];
    const float* b2l = (const float*)d_in[6];
    const float* W2r = (const float*)d_in[7];
    const float* Wm1 = (const float*)d_in[8];
    const float* bm1 = (const float*)d_in[9];
    const float* Wm2 = (const float*)d_in[10];
    const float* bm2 = (const float*)d_in[11];
    float*       out = (float*)d_out;

    void *p_agg, *p_h1, *p_h2, *p_ab, *p_inv;
    cudaGetSymbolAddress(&p_agg, g_agg);
    cudaGetSymbolAddress(&p_h1, g_h1);
    cudaGetSymbolAddress(&p_h2, g_h2);
    cudaGetSymbolAddress(&p_ab, g_ab);
    cudaGetSymbolAddress(&p_inv, g_inv);
    float*  agg = (float*)p_agg;
    float*  h1  = (float*)p_h1;
    float*  h2  = (float*)p_h2;
    __half* ab  = (__half*)p_ab;
    float*  inv = (float*)p_inv;

    const int ZB  = (N_NODES * FDIM + 255) / 256;      // 25000
    const int SB  = (E_EDGES * 32) / 256;              // 100000
    const int IB  = (N_NODES + 255) / 256;
    const int GBX = (N_NODES + 127) / 128;             // 391

    // ---- Layer 1 ----
    zero_all_kernel<<<ZB, 256>>>();
    scatter_kernel<true><<<SB, 256>>>(reinterpret_cast<const float4*>(x), ei);
    inv_kernel<<<IB, 256>>>();
    gemm_kernel<true, true, false, true, float><<<dim3(GBX, 2), 256>>>(
        agg, x, W1l, W1r, b1l, 128, h1, N_NODES, 128, inv);

    // ---- Layer 2 (cnt/inv reused) ----
    zero_agg_kernel<<<ZB, 256>>>();
    scatter_kernel<false><<<SB, 256>>>(reinterpret_cast<const float4*>(h1), ei);
    gemm_kernel<true, true, false, true, float><<<dim3(GBX, 2), 256>>>(
        agg, h1, W2l, W2r, b2l, 128, h2, N_NODES, 128, inv);

    // ---- Edge MLP, factorized: AB = h2 @ [Wm1_left | Wm1_right].T (+bm1 on A) ----
    gemm_kernel<false, false, true, false, __half><<<dim3(GBX, 8), 256>>>(
        h2, nullptr, Wm1, nullptr, bm1, 256, ab, N_NODES, 512, nullptr);

    edge_kernel<<<SB, 256>>>(ei, reinterpret_cast<const float4*>(Wm2), bm2, out);
}